// round 2
// baseline (speedup 1.0000x reference)
#include <cuda_runtime.h>
#include <math.h>

#define BB 2048
#define SS 200
#define DD 192
#define H1 64
#define H2 32
#define NT 128

// smem floats: qs(192) weff(12288) bias1(64) w2s(2048) w3s(32) b2s(32) score(256) wgt(256) red(128)
#define SMEM_FLOATS (192 + 12288 + 64 + 2048 + 32 + 32 + 256 + 256 + 128)

// Compute MLP scores for NS (1 or 2) key rows using shared weff/bias1/w2/w3.
template <int NS>
__device__ __forceinline__ void mlp_rows(const float* __restrict__ krow0,
                                         const float* __restrict__ krow1,
                                         const float* __restrict__ weff,
                                         const float* __restrict__ bias1,
                                         const float* __restrict__ w2s,
                                         const float* __restrict__ b2s,
                                         const float* __restrict__ w3s,
                                         float a1, float a2, float b3,
                                         float& sc0, float& sc1)
{
    float acc0[H1];
    float acc1[H1];
    #pragma unroll
    for (int h = 0; h < H1; h++) {
        acc0[h] = bias1[h];
        if (NS == 2) acc1[h] = bias1[h];
    }

    float4 kv0 = *reinterpret_cast<const float4*>(krow0);
    float4 kv1 = (NS == 2) ? *reinterpret_cast<const float4*>(krow1) : kv0;

    #pragma unroll 1
    for (int i = 0; i < DD; i += 4) {
        float4 n0 = kv0, n1 = kv1;
        if (i + 4 < DD) {
            n0 = *reinterpret_cast<const float4*>(krow0 + i + 4);
            if (NS == 2) n1 = *reinterpret_cast<const float4*>(krow1 + i + 4);
        }
        const float* kp0 = reinterpret_cast<const float*>(&kv0);
        const float* kp1 = reinterpret_cast<const float*>(&kv1);
        #pragma unroll
        for (int ii = 0; ii < 4; ii++) {
            float x0 = kp0[ii];
            float x1 = (NS == 2) ? kp1[ii] : 0.f;
            const float4* wrow = reinterpret_cast<const float4*>(weff + (i + ii) * H1);
            #pragma unroll
            for (int h4 = 0; h4 < H1 / 4; h4++) {
                float4 wv = wrow[h4];
                acc0[h4 * 4 + 0] = fmaf(x0, wv.x, acc0[h4 * 4 + 0]);
                acc0[h4 * 4 + 1] = fmaf(x0, wv.y, acc0[h4 * 4 + 1]);
                acc0[h4 * 4 + 2] = fmaf(x0, wv.z, acc0[h4 * 4 + 2]);
                acc0[h4 * 4 + 3] = fmaf(x0, wv.w, acc0[h4 * 4 + 3]);
                if (NS == 2) {
                    acc1[h4 * 4 + 0] = fmaf(x1, wv.x, acc1[h4 * 4 + 0]);
                    acc1[h4 * 4 + 1] = fmaf(x1, wv.y, acc1[h4 * 4 + 1]);
                    acc1[h4 * 4 + 2] = fmaf(x1, wv.z, acc1[h4 * 4 + 2]);
                    acc1[h4 * 4 + 3] = fmaf(x1, wv.w, acc1[h4 * 4 + 3]);
                }
            }
        }
        kv0 = n0;
        kv1 = n1;
    }

    // prelu 1
    #pragma unroll
    for (int h = 0; h < H1; h++) {
        acc0[h] = (acc0[h] >= 0.f) ? acc0[h] : a1 * acc0[h];
        if (NS == 2) acc1[h] = (acc1[h] >= 0.f) ? acc1[h] : a1 * acc1[h];
    }

    // layer 2: 64 -> 32
    float acc2_0[H2];
    float acc2_1[H2];
    #pragma unroll
    for (int k = 0; k < H2; k++) {
        acc2_0[k] = b2s[k];
        if (NS == 2) acc2_1[k] = b2s[k];
    }
    #pragma unroll 4
    for (int h = 0; h < H1; h++) {
        float h0 = acc0[h];
        float h1 = (NS == 2) ? acc1[h] : 0.f;
        const float4* wrow = reinterpret_cast<const float4*>(w2s + h * H2);
        #pragma unroll
        for (int k4 = 0; k4 < H2 / 4; k4++) {
            float4 wv = wrow[k4];
            acc2_0[k4 * 4 + 0] = fmaf(h0, wv.x, acc2_0[k4 * 4 + 0]);
            acc2_0[k4 * 4 + 1] = fmaf(h0, wv.y, acc2_0[k4 * 4 + 1]);
            acc2_0[k4 * 4 + 2] = fmaf(h0, wv.z, acc2_0[k4 * 4 + 2]);
            acc2_0[k4 * 4 + 3] = fmaf(h0, wv.w, acc2_0[k4 * 4 + 3]);
            if (NS == 2) {
                acc2_1[k4 * 4 + 0] = fmaf(h1, wv.x, acc2_1[k4 * 4 + 0]);
                acc2_1[k4 * 4 + 1] = fmaf(h1, wv.y, acc2_1[k4 * 4 + 1]);
                acc2_1[k4 * 4 + 2] = fmaf(h1, wv.z, acc2_1[k4 * 4 + 2]);
                acc2_1[k4 * 4 + 3] = fmaf(h1, wv.w, acc2_1[k4 * 4 + 3]);
            }
        }
    }
    #pragma unroll
    for (int k = 0; k < H2; k++) {
        acc2_0[k] = (acc2_0[k] >= 0.f) ? acc2_0[k] : a2 * acc2_0[k];
        if (NS == 2) acc2_1[k] = (acc2_1[k] >= 0.f) ? acc2_1[k] : a2 * acc2_1[k];
    }

    // layer 3: 32 -> 1
    float s0 = b3, s1 = b3;
    #pragma unroll
    for (int k = 0; k < H2; k++) {
        float w = w3s[k];
        s0 = fmaf(acc2_0[k], w, s0);
        if (NS == 2) s1 = fmaf(acc2_1[k], w, s1);
    }
    sc0 = s0;
    if (NS == 2) sc1 = s1;
}

__global__ __launch_bounds__(NT, 2)
void rich_attn_kernel(const float* __restrict__ query,
                      const float* __restrict__ keys,
                      const int*   __restrict__ kmask,
                      const float* __restrict__ W1,
                      const float* __restrict__ b1,
                      const float* __restrict__ a1p,
                      const float* __restrict__ W2,
                      const float* __restrict__ b2,
                      const float* __restrict__ a2p,
                      const float* __restrict__ W3,
                      const float* __restrict__ b3p,
                      float* __restrict__ out)
{
    extern __shared__ float sm[];
    float* qs    = sm;             // 192
    float* weff  = qs + 192;       // 12288 [i][h]
    float* bias1 = weff + 12288;   // 64
    float* w2s   = bias1 + 64;     // 2048 [h][k]
    float* w3s   = w2s + 2048;     // 32
    float* b2s   = w3s + 32;       // 32
    float* score = b2s + 32;       // 256
    float* wgt   = score + 256;    // 256
    float* red   = wgt + 256;      // 128

    const int tid = threadIdx.x;
    const int b   = blockIdx.x;

    const float a1 = a1p[0];
    const float a2 = a2p[0];
    const float b3 = b3p[0];

    // ---- load q, small weights ----
    for (int d = tid; d < DD; d += NT) qs[d] = query[(size_t)b * DD + d];
    for (int idx = tid; idx < H1 * H2; idx += NT) w2s[idx] = W2[idx];
    if (tid < H2) { w3s[tid] = W3[tid]; b2s[tid] = b2[tid]; }
    score[tid] = -INFINITY;
    score[tid + NT] = -INFINITY;
    wgt[tid] = 0.f;
    wgt[tid + NT] = 0.f;
    __syncthreads();

    // ---- build W_eff[i][h] = W1[i,h] + W1[576+i,h] + q_i*W1[384+i,h] ----
    for (int idx = tid; idx < DD * H1; idx += NT) {
        int i = idx >> 6;
        int h = idx & 63;
        weff[idx] = W1[idx] + W1[(576 + i) * H1 + h] + qs[i] * W1[(384 + i) * H1 + h];
    }
    // ---- bias1 partials: bias1[h] = b1[h] + sum_i q_i*(W1[192+i,h]-W1[576+i,h]) ----
    {
        int h = tid & 63;
        int half = tid >> 6;        // 0 or 1
        float acc = 0.f;
        int i0 = half * (DD / 2);
        #pragma unroll 4
        for (int i = i0; i < i0 + DD / 2; i++)
            acc = fmaf(qs[i], W1[(192 + i) * H1 + h] - W1[(576 + i) * H1 + h], acc);
        red[tid] = acc;
    }
    __syncthreads();
    if (tid < H1) bias1[tid] = b1[tid] + red[tid] + red[tid + 64];
    __syncthreads();

    // ---- MLP scores: warps 0-2 handle 2 rows each, warp 3 handles 1 ----
    const float* kbase = keys + (size_t)b * SS * DD;
    if (tid < 96) {
        int s0 = tid, s1 = tid + 96;
        float sc0, sc1;
        mlp_rows<2>(kbase + (size_t)s0 * DD, kbase + (size_t)s1 * DD,
                    weff, bias1, w2s, b2s, w3s, a1, a2, b3, sc0, sc1);
        int m0 = kmask[(size_t)b * SS + s0];
        int m1 = kmask[(size_t)b * SS + s1];
        score[s0] = m0 ? sc0 : -INFINITY;
        score[s1] = m1 ? sc1 : -INFINITY;
    } else {
        int s = tid + 96;   // 192..223
        if (s < SS) {
            float sc, dummy;
            mlp_rows<1>(kbase + (size_t)s * DD, kbase,
                        weff, bias1, w2s, b2s, w3s, a1, a2, b3, sc, dummy);
            int m = kmask[(size_t)b * SS + s];
            score[s] = m ? sc : -INFINITY;
        }
    }
    __syncthreads();

    // ---- softmax max ----
    red[tid] = fmaxf(score[tid], score[tid + NT]);
    __syncthreads();
    #pragma unroll
    for (int off = NT / 2; off > 0; off >>= 1) {
        if (tid < off) red[tid] = fmaxf(red[tid], red[tid + off]);
        __syncthreads();
    }
    const float m = red[0];
    __syncthreads();

    // ---- exp + sum ----
    float e0 = 0.f, e1 = 0.f;
    if (m > -INFINITY) {
        float sA = score[tid];
        float sB = score[tid + NT];
        e0 = (sA > -INFINITY) ? expf(sA - m) : 0.f;
        e1 = (sB > -INFINITY) ? expf(sB - m) : 0.f;
    }
    wgt[tid] = e0;
    wgt[tid + NT] = e1;
    red[tid] = e0 + e1;
    __syncthreads();
    #pragma unroll
    for (int off = NT / 2; off > 0; off >>= 1) {
        if (tid < off) red[tid] += red[tid + off];
        __syncthreads();
    }
    const float ssum = red[0];
    __syncthreads();
    const float inv = (ssum > 0.f) ? (1.f / ssum) : 0.f;

    float w0 = e0 * inv;
    float w1 = e1 * inv;
    wgt[tid] = w0;
    wgt[tid + NT] = w1;
    if (tid < SS)      out[(size_t)BB * DD + (size_t)b * SS + tid]      = w0;
    if (tid + NT < SS) out[(size_t)BB * DD + (size_t)b * SS + tid + NT] = w1;
    __syncthreads();

    // ---- weighted sum: out[b,d] = sum_s wgt[s]*keys[b,s,d] ----
    for (int d = tid; d < DD; d += NT) {
        const float* kb = kbase + d;
        float acc = 0.f;
        #pragma unroll 8
        for (int si = 0; si < SS; si++)
            acc = fmaf(wgt[si], kb[(size_t)si * DD], acc);
        out[(size_t)b * DD + d] = acc;
    }
}

extern "C" void kernel_launch(void* const* d_in, const int* in_sizes, int n_in,
                              void* d_out, int out_size)
{
    const float* query = (const float*)d_in[0];
    const float* keys  = (const float*)d_in[1];
    const int*   mask  = (const int*)  d_in[2];
    const float* W1    = (const float*)d_in[3];
    const float* b1    = (const float*)d_in[4];
    const float* a1    = (const float*)d_in[5];
    const float* W2    = (const float*)d_in[6];
    const float* b2    = (const float*)d_in[7];
    const float* a2    = (const float*)d_in[8];
    const float* W3    = (const float*)d_in[9];
    const float* b3    = (const float*)d_in[10];
    float* out = (float*)d_out;

    static bool attr_set = false;
    if (!attr_set) {
        cudaFuncSetAttribute(rich_attn_kernel,
                             cudaFuncAttributeMaxDynamicSharedMemorySize,
                             SMEM_FLOATS * sizeof(float));
        attr_set = true;
    }

    rich_attn_kernel<<<BB, NT, SMEM_FLOATS * sizeof(float)>>>(
        query, keys, mask, W1, b1, a1, W2, b2, a2, W3, b3, out);
}

// round 3
// speedup vs baseline: 4.0441x; 4.0441x over previous
#include <cuda_runtime.h>
#include <math.h>
#include <stdint.h>

#define BB 2048
#define SS 200
#define DD 192
#define H1 64
#define H2 32
#define NT 256
#define KT 32
#define NTILE 6
#define APAD 204   // padded floats per k-row of A tile (204%4==0 for LDS.128 align, 204%32=12 -> few STS conflicts)

typedef unsigned long long ull;

// ---- smem layout (floats) ----
#define SM_WEFF 0                         // [192][64] = 12288
#define SM_ABUF (SM_WEFF + 12288)         // 2 * KT * APAD = 13056 ; overlaid by H[200][64]=12800 after GEMM
#define SM_QS   (SM_ABUF + 2*KT*APAD)     // 192
#define SM_B1   (SM_QS + 192)             // 64
#define SM_W2   (SM_B1 + 64)              // 2048  [h][k]
#define SM_W3   (SM_W2 + 2048)            // 32
#define SM_B2   (SM_W3 + 32)              // 32
#define SM_SC   (SM_B2 + 32)              // 256
#define SM_WGT  (SM_SC + 256)             // 256
#define SM_RED  (SM_WGT + 256)            // 256
#define SMEM_FLOATS (SM_RED + 256)

__device__ __forceinline__ void cp4(uint32_t dst, const float* src) {
    asm volatile("cp.async.ca.shared.global [%0], [%1], 4;" :: "r"(dst), "l"(src));
}
__device__ __forceinline__ void cp_commit() { asm volatile("cp.async.commit_group;" ::: "memory"); }
__device__ __forceinline__ void cp_wait1()  { asm volatile("cp.async.wait_group 1;" ::: "memory"); }
__device__ __forceinline__ void cp_wait0()  { asm volatile("cp.async.wait_group 0;" ::: "memory"); }

__device__ __forceinline__ ull pk2(float x) {          // pack (x,x) into f32x2
    ull r; asm("mov.b64 %0, {%1, %1};" : "=l"(r) : "f"(x)); return r;
}
__device__ __forceinline__ void fma2(ull& d, ull a, ull b) {
    asm("fma.rn.f32x2 %0, %1, %2, %0;" : "+l"(d) : "l"(a), "l"(b));
}
__device__ __forceinline__ float2 up2(ull v) {
    float2 r; asm("mov.b64 {%0, %1}, %2;" : "=f"(r.x), "=f"(r.y) : "l"(v)); return r;
}

__global__ __launch_bounds__(NT, 1)
void rich_attn_kernel(const float* __restrict__ query,
                      const float* __restrict__ keys,
                      const int*   __restrict__ kmask,
                      const float* __restrict__ W1,
                      const float* __restrict__ b1,
                      const float* __restrict__ a1p,
                      const float* __restrict__ W2,
                      const float* __restrict__ b2,
                      const float* __restrict__ a2p,
                      const float* __restrict__ W3,
                      const float* __restrict__ b3p,
                      float* __restrict__ out)
{
    extern __shared__ float sm[];
    const int tid = threadIdx.x;
    const int b   = blockIdx.x;

    const float a1 = a1p[0];
    const float a2 = a2p[0];
    const float b3 = b3p[0];

    const float* kbase = keys + (size_t)b * SS * DD;
    uint32_t smem_u32;
    { void* p = sm; smem_u32 = (uint32_t)__cvta_generic_to_shared(p); }

    // ---------- issue prefetch of keys tiles 0,1 (before any compute) ----------
    #pragma unroll
    for (int t = 0; t < 2; t++) {
        const float* g = kbase + t * KT;
        uint32_t abase = smem_u32 + (SM_ABUF + t * KT * APAD) * 4;
        #pragma unroll
        for (int j = 0; j < (SS * KT) / NT; j++) {   // 25 per thread
            int e = tid + j * NT;
            int s = e >> 5;            // 0..199
            int k = e & 31;
            cp4(abase + (uint32_t)(k * APAD + s) * 4, g + (size_t)s * DD + k);
        }
        cp_commit();
    }

    // ---------- q, small weights ----------
    float* qs    = sm + SM_QS;
    float* weff  = sm + SM_WEFF;
    float* bias1 = sm + SM_B1;
    float* w2s   = sm + SM_W2;
    float* w3s   = sm + SM_W3;
    float* b2s   = sm + SM_B2;
    float* score = sm + SM_SC;
    float* wgt   = sm + SM_WGT;
    float* red   = sm + SM_RED;

    if (tid < DD) qs[tid] = query[(size_t)b * DD + tid];
    for (int idx = tid; idx < H1 * H2; idx += NT) w2s[idx] = W2[idx];
    if (tid < H2) { w3s[tid] = W3[tid]; b2s[tid] = b2[tid]; }
    score[tid] = -INFINITY;
    wgt[tid] = 0.f;
    __syncthreads();   // qs visible for weff build

    // ---------- weff[i][h] = W1[i,h] + W1[576+i,h] + q_i * W1[384+i,h] ----------
    for (int idx = tid; idx < DD * H1; idx += NT) {
        int i = idx >> 6;
        int h = idx & 63;
        weff[idx] = W1[idx] + W1[(576 + i) * H1 + h] + qs[i] * W1[(384 + i) * H1 + h];
    }
    // ---------- bias1[h] = b1[h] + sum_i q_i*(W1[192+i,h]-W1[576+i,h]) ----------
    {
        int h = tid & 63;
        int q4 = tid >> 6;                   // 0..3, 48 i each
        float acc = 0.f;
        int i0 = q4 * 48;
        #pragma unroll 4
        for (int i = i0; i < i0 + 48; i++)
            acc = fmaf(qs[i], W1[(192 + i) * H1 + h] - W1[(576 + i) * H1 + h], acc);
        red[tid] = acc;
    }
    __syncthreads();
    if (tid < H1)
        bias1[tid] = b1[tid] + red[tid] + red[tid + 64] + red[tid + 128] + red[tid + 192];
    __syncthreads();

    // ---------- main GEMM: H(200x64) = keys(200x192) @ weff(192x64) ----------
    const int sg = tid >> 3;        // 0..31 (only 0..24 active)
    const int hg = tid & 7;         // 0..7
    const int s0 = sg * 8;
    const int h0 = hg * 8;
    const bool comp = (tid < 200);

    ull acc[8][4];
    if (comp) {
        ulonglong2 bi0 = *reinterpret_cast<const ulonglong2*>(bias1 + h0);
        ulonglong2 bi1 = *reinterpret_cast<const ulonglong2*>(bias1 + h0 + 4);
        #pragma unroll
        for (int j = 0; j < 8; j++) {
            acc[j][0] = bi0.x; acc[j][1] = bi0.y;
            acc[j][2] = bi1.x; acc[j][3] = bi1.y;
        }
    }

    for (int t = 0; t < NTILE; t++) {
        if (t == NTILE - 1) cp_wait0(); else cp_wait1();
        __syncthreads();

        if (comp) {
            const float* At = sm + SM_ABUF + (t & 1) * KT * APAD;
            const float* Wt = weff + t * KT * H1;
            #pragma unroll 4
            for (int k = 0; k < KT; k++) {
                const float* ar = At + k * APAD + s0;
                float4 av0 = *reinterpret_cast<const float4*>(ar);
                float4 av1 = *reinterpret_cast<const float4*>(ar + 4);
                const float* wr = Wt + k * H1 + h0;
                ulonglong2 bv0 = *reinterpret_cast<const ulonglong2*>(wr);
                ulonglong2 bv1 = *reinterpret_cast<const ulonglong2*>(wr + 4);

                ull x[8];
                x[0] = pk2(av0.x); x[1] = pk2(av0.y); x[2] = pk2(av0.z); x[3] = pk2(av0.w);
                x[4] = pk2(av1.x); x[5] = pk2(av1.y); x[6] = pk2(av1.z); x[7] = pk2(av1.w);
                #pragma unroll
                for (int j = 0; j < 8; j++) {
                    fma2(acc[j][0], x[j], bv0.x);
                    fma2(acc[j][1], x[j], bv0.y);
                    fma2(acc[j][2], x[j], bv1.x);
                    fma2(acc[j][3], x[j], bv1.y);
                }
            }
        }
        __syncthreads();   // all reads of this buffer done before refill

        if (t + 2 < NTILE) {
            const float* g = kbase + (t + 2) * KT;
            uint32_t abase = smem_u32 + (SM_ABUF + (t & 1) * KT * APAD) * 4;
            #pragma unroll
            for (int j = 0; j < (SS * KT) / NT; j++) {
                int e = tid + j * NT;
                int s = e >> 5;
                int k = e & 31;
                cp4(abase + (uint32_t)(k * APAD + s) * 4, g + (size_t)s * DD + k);
            }
            cp_commit();
        }
    }

    // ---------- prelu1 + store H[200][64] into smem (overlay A buffers) ----------
    float* Hs = sm + SM_ABUF;
    if (comp) {
        #pragma unroll
        for (int j = 0; j < 8; j++) {
            float4 o0, o1;
            float2 p;
            p = up2(acc[j][0]); o0.x = (p.x >= 0.f) ? p.x : a1 * p.x; o0.y = (p.y >= 0.f) ? p.y : a1 * p.y;
            p = up2(acc[j][1]); o0.z = (p.x >= 0.f) ? p.x : a1 * p.x; o0.w = (p.y >= 0.f) ? p.y : a1 * p.y;
            p = up2(acc[j][2]); o1.x = (p.x >= 0.f) ? p.x : a1 * p.x; o1.y = (p.y >= 0.f) ? p.y : a1 * p.y;
            p = up2(acc[j][3]); o1.z = (p.x >= 0.f) ? p.x : a1 * p.x; o1.w = (p.y >= 0.f) ? p.y : a1 * p.y;
            float* hrow = Hs + (size_t)(s0 + j) * H1 + h0;
            *reinterpret_cast<float4*>(hrow)     = o0;
            *reinterpret_cast<float4*>(hrow + 4) = o1;
        }
    }
    __syncthreads();

    // ---------- layers 2+3 per s (f32x2) ----------
    if (tid < SS) {
        const float* hrow = Hs + (size_t)tid * H1;
        ull acc2[16];
        {
            const ulonglong2* bp = reinterpret_cast<const ulonglong2*>(b2s);
            #pragma unroll
            for (int j = 0; j < 8; j++) { acc2[2*j] = bp[j].x; acc2[2*j+1] = bp[j].y; }
        }
        #pragma unroll 4
        for (int h = 0; h < H1; h++) {
            ull xx = pk2(hrow[h]);
            const ulonglong2* wr = reinterpret_cast<const ulonglong2*>(w2s + h * H2);
            #pragma unroll
            for (int j4 = 0; j4 < 8; j4++) {
                ulonglong2 wv = wr[j4];
                // careful: ulonglong2 is 16B; w2 row is 32 floats = 8 ulonglong2
                fma2(acc2[2*j4],   xx, wv.x);
                fma2(acc2[2*j4+1], xx, wv.y);
            }
        }
        float sc = b3;
        #pragma unroll
        for (int j = 0; j < 16; j++) {
            float2 p = up2(acc2[j]);
            float v0 = (p.x >= 0.f) ? p.x : a2 * p.x;
            float v1 = (p.y >= 0.f) ? p.y : a2 * p.y;
            sc = fmaf(v0, w3s[2*j], sc);
            sc = fmaf(v1, w3s[2*j + 1], sc);
        }
        int mv = kmask[(size_t)b * SS + tid];
        score[tid] = mv ? sc : -INFINITY;
    }
    __syncthreads();

    // ---------- softmax over 256-padded score ----------
    red[tid] = score[tid];
    __syncthreads();
    #pragma unroll
    for (int off = NT / 2; off > 0; off >>= 1) {
        if (tid < off) red[tid] = fmaxf(red[tid], red[tid + off]);
        __syncthreads();
    }
    const float m = red[0];
    __syncthreads();

    float e = 0.f;
    if (m > -INFINITY) {
        float svv = score[tid];
        e = (svv > -INFINITY) ? expf(svv - m) : 0.f;
    }
    red[tid] = e;
    __syncthreads();
    #pragma unroll
    for (int off = NT / 2; off > 0; off >>= 1) {
        if (tid < off) red[tid] += red[tid + off];
        __syncthreads();
    }
    const float ssum = red[0];
    __syncthreads();
    const float inv = (ssum > 0.f) ? (1.f / ssum) : 0.f;

    float wv = e * inv;
    wgt[tid] = wv;
    if (tid < SS) out[(size_t)BB * DD + (size_t)b * SS + tid] = wv;
    __syncthreads();

    // ---------- weighted sum: out[b,d] = sum_s wgt[s]*keys[b,s,d] ----------
    if (tid < DD) {
        const float* kb = kbase + tid;
        float accw = 0.f;
        #pragma unroll 8
        for (int si = 0; si < SS; si++)
            accw = fmaf(wgt[si], kb[(size_t)si * DD], accw);
        out[(size_t)b * DD + tid] = accw;
    }
}

extern "C" void kernel_launch(void* const* d_in, const int* in_sizes, int n_in,
                              void* d_out, int out_size)
{
    const float* query = (const float*)d_in[0];
    const float* keys  = (const float*)d_in[1];
    const int*   mask  = (const int*)  d_in[2];
    const float* W1    = (const float*)d_in[3];
    const float* b1    = (const float*)d_in[4];
    const float* a1    = (const float*)d_in[5];
    const float* W2    = (const float*)d_in[6];
    const float* b2    = (const float*)d_in[7];
    const float* a2    = (const float*)d_in[8];
    const float* W3    = (const float*)d_in[9];
    const float* b3    = (const float*)d_in[10];
    float* out = (float*)d_out;

    static bool attr_set = false;
    if (!attr_set) {
        cudaFuncSetAttribute(rich_attn_kernel,
                             cudaFuncAttributeMaxDynamicSharedMemorySize,
                             SMEM_FLOATS * sizeof(float));
        attr_set = true;
    }

    rich_attn_kernel<<<BB, NT, SMEM_FLOATS * sizeof(float)>>>(
        query, keys, mask, W1, b1, a1, W2, b2, a2, W3, b3, out);
}